// round 1
// baseline (speedup 1.0000x reference)
#include <cuda_runtime.h>
#include <math.h>

#define BB 4
#define SS 2048
#define DD 1024
#define HH 16
#define HDIM 64
#define MR (BB*SS)          // 8192 rows

// Scratch (allocation-free: device globals)
__device__ float g_q[(size_t)BB*HH*SS*HDIM];   // 32 MB, head-major, pre-scaled by 0.125
__device__ float g_k[(size_t)BB*HH*SS*HDIM];
__device__ float g_v[(size_t)BB*HH*SS*HDIM];
__device__ float g_attn[(size_t)MR*DD];        // [B*S, D] for out-proj

// ---------------------------------------------------------------------------
// GEMM1: X[8192,1024] @ Wqkv[1024,3072] + b_qkv, scatter to g_q/g_k/g_v
// 128x128 block tile, BK=16, 8x8 per thread, 256 threads
// ---------------------------------------------------------------------------
__global__ __launch_bounds__(256, 2) void qkv_gemm(const float* __restrict__ A,
                                                   const float* __restrict__ Bw,
                                                   const float* __restrict__ bias) {
    const int BK = 16;
    __shared__ float As[BK][128];
    __shared__ float Bs[BK][128];
    const int tid = threadIdx.x;
    const int m0 = blockIdx.y * 128, n0 = blockIdx.x * 128;
    const int tR = tid >> 4, tC = tid & 15;
    const int aRow = tid >> 2, aCol = (tid & 3) << 2;
    const int bRow = tid >> 5, bCol = (tid & 31) << 2;
    const int N = 3 * DD;

    float acc[8][8];
#pragma unroll
    for (int i = 0; i < 8; i++)
#pragma unroll
        for (int j = 0; j < 8; j++) acc[i][j] = 0.f;

    for (int k0 = 0; k0 < DD; k0 += BK) {
#pragma unroll
        for (int rr = 0; rr < 2; rr++) {
            int r = aRow + rr * 64;
            float4 t = *(const float4*)(A + (size_t)(m0 + r) * DD + k0 + aCol);
            As[aCol + 0][r] = t.x; As[aCol + 1][r] = t.y;
            As[aCol + 2][r] = t.z; As[aCol + 3][r] = t.w;
        }
#pragma unroll
        for (int rr = 0; rr < 2; rr++) {
            int r = bRow + rr * 8;
            *(float4*)&Bs[r][bCol] =
                *(const float4*)(Bw + (size_t)(k0 + r) * N + n0 + bCol);
        }
        __syncthreads();
#pragma unroll
        for (int k = 0; k < BK; k++) {
            float a[8], b[8];
            *(float4*)(a)     = *(float4*)&As[k][tR * 8];
            *(float4*)(a + 4) = *(float4*)&As[k][tR * 8 + 4];
            *(float4*)(b)     = *(float4*)&Bs[k][tC * 8];
            *(float4*)(b + 4) = *(float4*)&Bs[k][tC * 8 + 4];
#pragma unroll
            for (int i = 0; i < 8; i++)
#pragma unroll
                for (int j = 0; j < 8; j++) acc[i][j] = fmaf(a[i], b[j], acc[i][j]);
        }
        __syncthreads();
    }

    // Epilogue: bias, q-scale, scatter head-major
#pragma unroll
    for (int i = 0; i < 8; i++) {
        int row = m0 + tR * 8 + i;
        int b_ = row >> 11, s_ = row & 2047;
#pragma unroll
        for (int j = 0; j < 8; j++) {
            int col = n0 + tC * 8 + j;
            float v = acc[i][j] + bias[col];
            int part = col >> 10;
            int d = col & 1023;
            int h = d >> 6, hd = d & 63;
            size_t dst = ((size_t)(b_ * HH + h) * SS + s_) * HDIM + hd;
            if (part == 0)      g_q[dst] = v * 0.125f;   // 1/sqrt(64)
            else if (part == 1) g_k[dst] = v;
            else                g_v[dst] = v;
        }
    }
}

// ---------------------------------------------------------------------------
// GEMM2: g_attn[8192,1024] @ Wout[1024,1024] + b_out -> out
// ---------------------------------------------------------------------------
__global__ __launch_bounds__(256, 2) void out_gemm(const float* __restrict__ Bw,
                                                   const float* __restrict__ bias,
                                                   float* __restrict__ C) {
    const int BK = 16;
    __shared__ float As[BK][128];
    __shared__ float Bs[BK][128];
    const int tid = threadIdx.x;
    const int m0 = blockIdx.y * 128, n0 = blockIdx.x * 128;
    const int tR = tid >> 4, tC = tid & 15;
    const int aRow = tid >> 2, aCol = (tid & 3) << 2;
    const int bRow = tid >> 5, bCol = (tid & 31) << 2;
    const int N = DD;
    const float* A = g_attn;

    float acc[8][8];
#pragma unroll
    for (int i = 0; i < 8; i++)
#pragma unroll
        for (int j = 0; j < 8; j++) acc[i][j] = 0.f;

    for (int k0 = 0; k0 < DD; k0 += BK) {
#pragma unroll
        for (int rr = 0; rr < 2; rr++) {
            int r = aRow + rr * 64;
            float4 t = *(const float4*)(A + (size_t)(m0 + r) * DD + k0 + aCol);
            As[aCol + 0][r] = t.x; As[aCol + 1][r] = t.y;
            As[aCol + 2][r] = t.z; As[aCol + 3][r] = t.w;
        }
#pragma unroll
        for (int rr = 0; rr < 2; rr++) {
            int r = bRow + rr * 8;
            *(float4*)&Bs[r][bCol] =
                *(const float4*)(Bw + (size_t)(k0 + r) * N + n0 + bCol);
        }
        __syncthreads();
#pragma unroll
        for (int k = 0; k < BK; k++) {
            float a[8], b[8];
            *(float4*)(a)     = *(float4*)&As[k][tR * 8];
            *(float4*)(a + 4) = *(float4*)&As[k][tR * 8 + 4];
            *(float4*)(b)     = *(float4*)&Bs[k][tC * 8];
            *(float4*)(b + 4) = *(float4*)&Bs[k][tC * 8 + 4];
#pragma unroll
            for (int i = 0; i < 8; i++)
#pragma unroll
                for (int j = 0; j < 8; j++) acc[i][j] = fmaf(a[i], b[j], acc[i][j]);
        }
        __syncthreads();
    }

#pragma unroll
    for (int i = 0; i < 8; i++) {
        int row = m0 + tR * 8 + i;
#pragma unroll
        for (int j = 0; j < 4; j++) {
            // grouped float4 stores
        }
        float4 v0, v1;
        v0.x = acc[i][0] + bias[n0 + tC * 8 + 0];
        v0.y = acc[i][1] + bias[n0 + tC * 8 + 1];
        v0.z = acc[i][2] + bias[n0 + tC * 8 + 2];
        v0.w = acc[i][3] + bias[n0 + tC * 8 + 3];
        v1.x = acc[i][4] + bias[n0 + tC * 8 + 4];
        v1.y = acc[i][5] + bias[n0 + tC * 8 + 5];
        v1.z = acc[i][6] + bias[n0 + tC * 8 + 6];
        v1.w = acc[i][7] + bias[n0 + tC * 8 + 7];
        *(float4*)(C + (size_t)row * DD + n0 + tC * 8)     = v0;
        *(float4*)(C + (size_t)row * DD + n0 + tC * 8 + 4) = v1;
    }
}

// ---------------------------------------------------------------------------
// Flash attention, fp32, causal. 64x64 tiles. 256 threads:
// thread = (r = tid/4, quarter q = tid%4 owning cols q*16..q*16+15)
// ---------------------------------------------------------------------------
#define QS_STRIDE 65
#define KT_STRIDE 68
#define PS_STRIDE 65
#define SMEM_FLOATS (64*QS_STRIDE + 64*KT_STRIDE + 64*64 + 64*PS_STRIDE)

__global__ __launch_bounds__(256, 2) void attn_kernel() {
    extern __shared__ float sm[];
    float* Qs = sm;                          // [64][65]
    float* Kt = Qs + 64 * QS_STRIDE;         // [64(hd)][68] transposed K
    float* Vs = Kt + 64 * KT_STRIDE;         // [64(seq)][64(hd)]
    float* Ps = Vs + 64 * 64;                // [64][65]

    const int qt = blockIdx.x;               // query tile 0..31
    const int bh = blockIdx.y;               // b*H + h
    const int tid = threadIdx.x;
    const int r = tid >> 2;                  // query row in tile
    const int c0 = (tid & 3) * 16;           // col quarter base

    const float* Qg = g_q + (size_t)bh * SS * HDIM;
    const float* Kg = g_k + (size_t)bh * SS * HDIM;
    const float* Vg = g_v + (size_t)bh * SS * HDIM;

    // load Q tile (already scaled by 0.125)
    for (int t = tid; t < 64 * 16; t += 256) {
        int rr = t >> 4, cc = (t & 15) * 4;
        float4 v = *(const float4*)(Qg + ((size_t)(qt * 64 + rr)) * HDIM + cc);
        Qs[rr * QS_STRIDE + cc + 0] = v.x;
        Qs[rr * QS_STRIDE + cc + 1] = v.y;
        Qs[rr * QS_STRIDE + cc + 2] = v.z;
        Qs[rr * QS_STRIDE + cc + 3] = v.w;
    }
    __syncthreads();

    float m = -INFINITY, l = 0.f;
    float o[16];
#pragma unroll
    for (int i = 0; i < 16; i++) o[i] = 0.f;

    for (int j = 0; j <= qt; j++) {
        // load K (transposed) and V tiles
        for (int t = tid; t < 64 * 16; t += 256) {
            int rr = t >> 4, cc = (t & 15) * 4;
            size_t gofs = ((size_t)(j * 64 + rr)) * HDIM + cc;
            float4 kv = *(const float4*)(Kg + gofs);
            Kt[(cc + 0) * KT_STRIDE + rr] = kv.x;
            Kt[(cc + 1) * KT_STRIDE + rr] = kv.y;
            Kt[(cc + 2) * KT_STRIDE + rr] = kv.z;
            Kt[(cc + 3) * KT_STRIDE + rr] = kv.w;
            float4 vv = *(const float4*)(Vg + gofs);
            *(float4*)&Vs[rr * 64 + cc] = vv;
        }
        __syncthreads();

        // S = Q @ K^T for my 1x16 strip
        float s[16];
#pragma unroll
        for (int i = 0; i < 16; i++) s[i] = 0.f;
#pragma unroll 8
        for (int k = 0; k < 64; k++) {
            float qv = Qs[r * QS_STRIDE + k];
            float4 k0 = *(float4*)&Kt[k * KT_STRIDE + c0];
            float4 k1 = *(float4*)&Kt[k * KT_STRIDE + c0 + 4];
            float4 k2 = *(float4*)&Kt[k * KT_STRIDE + c0 + 8];
            float4 k3 = *(float4*)&Kt[k * KT_STRIDE + c0 + 12];
            s[0]  = fmaf(qv, k0.x, s[0]);  s[1]  = fmaf(qv, k0.y, s[1]);
            s[2]  = fmaf(qv, k0.z, s[2]);  s[3]  = fmaf(qv, k0.w, s[3]);
            s[4]  = fmaf(qv, k1.x, s[4]);  s[5]  = fmaf(qv, k1.y, s[5]);
            s[6]  = fmaf(qv, k1.z, s[6]);  s[7]  = fmaf(qv, k1.w, s[7]);
            s[8]  = fmaf(qv, k2.x, s[8]);  s[9]  = fmaf(qv, k2.y, s[9]);
            s[10] = fmaf(qv, k2.z, s[10]); s[11] = fmaf(qv, k2.w, s[11]);
            s[12] = fmaf(qv, k3.x, s[12]); s[13] = fmaf(qv, k3.y, s[13]);
            s[14] = fmaf(qv, k3.z, s[14]); s[15] = fmaf(qv, k3.w, s[15]);
        }

        // causal mask on the diagonal tile
        if (j == qt) {
#pragma unroll
            for (int i = 0; i < 16; i++)
                if (c0 + i > r) s[i] = -INFINITY;
        }

        // online softmax (row spread over 4 lanes)
        float mt = s[0];
#pragma unroll
        for (int i = 1; i < 16; i++) mt = fmaxf(mt, s[i]);
        mt = fmaxf(mt, __shfl_xor_sync(0xffffffffu, mt, 1));
        mt = fmaxf(mt, __shfl_xor_sync(0xffffffffu, mt, 2));
        float mnew = fmaxf(m, mt);
        float alpha = __expf(m - mnew);
        float rs = 0.f;
#pragma unroll
        for (int i = 0; i < 16; i++) {
            float p = __expf(s[i] - mnew);
            rs += p;
            Ps[r * PS_STRIDE + c0 + i] = p;
        }
        rs += __shfl_xor_sync(0xffffffffu, rs, 1);
        rs += __shfl_xor_sync(0xffffffffu, rs, 2);
        l = l * alpha + rs;
        m = mnew;
#pragma unroll
        for (int i = 0; i < 16; i++) o[i] *= alpha;
        __syncthreads();

        // O += P @ V
#pragma unroll 8
        for (int k = 0; k < 64; k++) {
            float p = Ps[r * PS_STRIDE + k];
            float4 v0 = *(float4*)&Vs[k * 64 + c0];
            float4 v1 = *(float4*)&Vs[k * 64 + c0 + 4];
            float4 v2 = *(float4*)&Vs[k * 64 + c0 + 8];
            float4 v3 = *(float4*)&Vs[k * 64 + c0 + 12];
            o[0]  = fmaf(p, v0.x, o[0]);  o[1]  = fmaf(p, v0.y, o[1]);
            o[2]  = fmaf(p, v0.z, o[2]);  o[3]  = fmaf(p, v0.w, o[3]);
            o[4]  = fmaf(p, v1.x, o[4]);  o[5]  = fmaf(p, v1.y, o[5]);
            o[6]  = fmaf(p, v1.z, o[6]);  o[7]  = fmaf(p, v1.w, o[7]);
            o[8]  = fmaf(p, v2.x, o[8]);  o[9]  = fmaf(p, v2.y, o[9]);
            o[10] = fmaf(p, v2.z, o[10]); o[11] = fmaf(p, v2.w, o[11]);
            o[12] = fmaf(p, v3.x, o[12]); o[13] = fmaf(p, v3.y, o[13]);
            o[14] = fmaf(p, v3.z, o[14]); o[15] = fmaf(p, v3.w, o[15]);
        }
        __syncthreads();
    }

    float inv = 1.f / l;
#pragma unroll
    for (int i = 0; i < 16; i++) o[i] *= inv;

    int b_ = bh >> 4, h = bh & 15;
    float* op = g_attn + ((size_t)(b_ * SS + qt * 64 + r)) * DD + h * 64 + c0;
    *(float4*)(op)      = make_float4(o[0],  o[1],  o[2],  o[3]);
    *(float4*)(op + 4)  = make_float4(o[4],  o[5],  o[6],  o[7]);
    *(float4*)(op + 8)  = make_float4(o[8],  o[9],  o[10], o[11]);
    *(float4*)(op + 12) = make_float4(o[12], o[13], o[14], o[15]);
}

// ---------------------------------------------------------------------------
extern "C" void kernel_launch(void* const* d_in, const int* in_sizes, int n_in,
                              void* d_out, int out_size) {
    const float* x     = (const float*)d_in[0];
    const float* W_qkv = (const float*)d_in[1];
    const float* b_qkv = (const float*)d_in[2];
    const float* W_out = (const float*)d_in[3];
    const float* b_out = (const float*)d_in[4];
    float* out = (float*)d_out;

    dim3 g1(3 * DD / 128, MR / 128);    // 24 x 64
    qkv_gemm<<<g1, 256>>>(x, W_qkv, b_qkv);

    size_t smem = (size_t)SMEM_FLOATS * sizeof(float);   // ~67 KB
    cudaFuncSetAttribute(attn_kernel,
                         cudaFuncAttributeMaxDynamicSharedMemorySize, (int)smem);
    attn_kernel<<<dim3(SS / 64, BB * HH), 256, smem>>>();

    dim3 g2(DD / 128, MR / 128);        // 8 x 64
    out_gemm<<<g2, 256>>>(W_out, b_out, out);
}

// round 6
// speedup vs baseline: 1.2092x; 1.2092x over previous
#include <cuda_runtime.h>
#include <cuda_bf16.h>
#include <math.h>
#include <stdint.h>

#define BB 4
#define SS 2048
#define DD 1024
#define HH 16
#define HDIM 64
#define MR (BB*SS)          // 8192 rows

// Scratch (allocation-free: device globals)
__device__ float g_q[(size_t)BB*HH*SS*HDIM];   // head-major, pre-scaled by 0.125
__device__ float g_k[(size_t)BB*HH*SS*HDIM];
__device__ float g_v[(size_t)BB*HH*SS*HDIM];
__device__ float g_attn[(size_t)MR*DD];        // [B*S, D] for out-proj

// ---------------------------------------------------------------------------
// Warp-MMA helpers (baseline PTX ISA only: works on plain sm_103 target)
// ---------------------------------------------------------------------------
__device__ __forceinline__ uint32_t smem_u32(const void* p) {
    uint32_t a;
    asm("{ .reg .u64 t; cvta.to.shared.u64 t, %1; cvt.u32.u64 %0, t; }"
        : "=r"(a) : "l"(p));
    return a;
}

__device__ __forceinline__ void ldsm4(uint32_t addr, uint32_t r[4]) {
    asm volatile("ldmatrix.sync.aligned.m8n8.x4.shared.b16 {%0,%1,%2,%3}, [%4];"
                 : "=r"(r[0]), "=r"(r[1]), "=r"(r[2]), "=r"(r[3]) : "r"(addr) : "memory");
}
__device__ __forceinline__ void ldsm4t(uint32_t addr, uint32_t r[4]) {
    asm volatile("ldmatrix.sync.aligned.m8n8.x4.trans.shared.b16 {%0,%1,%2,%3}, [%4];"
                 : "=r"(r[0]), "=r"(r[1]), "=r"(r[2]), "=r"(r[3]) : "r"(addr) : "memory");
}
__device__ __forceinline__ void mma16816(float d[4], const uint32_t a[4],
                                         uint32_t b0, uint32_t b1) {
    asm volatile(
        "mma.sync.aligned.m16n8k16.row.col.f32.bf16.bf16.f32 "
        "{%0,%1,%2,%3}, {%4,%5,%6,%7}, {%8,%9}, {%0,%1,%2,%3};"
        : "+f"(d[0]), "+f"(d[1]), "+f"(d[2]), "+f"(d[3])
        : "r"(a[0]), "r"(a[1]), "r"(a[2]), "r"(a[3]), "r"(b0), "r"(b1));
}

// split two fp32 into packed bf16 hi pair + lo (residual) pair
__device__ __forceinline__ void split2(float x, float y, uint32_t& h, uint32_t& l) {
    __nv_bfloat16 hx = __float2bfloat16(x), hy = __float2bfloat16(y);
    float rx = x - __bfloat162float(hx);
    float ry = y - __bfloat162float(hy);
    __nv_bfloat16 lx = __float2bfloat16(rx), ly = __float2bfloat16(ry);
    h = (uint32_t)__bfloat16_as_ushort(hx) | ((uint32_t)__bfloat16_as_ushort(hy) << 16);
    l = (uint32_t)__bfloat16_as_ushort(lx) | ((uint32_t)__bfloat16_as_ushort(ly) << 16);
}

// ---------------------------------------------------------------------------
// HMMA GEMM: C[8192, N] = A[8192,1024] @ W[1024,N] + bias, bf16x3 split.
// CTA tile 128x128, BK=64 fp32 per chunk (16 chunks). 8 warps, warp tile 32x64.
// A smem: row-major [m][k] bf16, row stride 144B. W smem: [k][n] bf16 (gmem
// layout), row stride 272B, consumed via ldmatrix.trans.
// MODE 0: A=x, scatter to g_q/g_k/g_v (q scaled 0.125). MODE 1: A=g_attn -> C.
// ---------------------------------------------------------------------------
#define A_RS 144              // bytes per m-row (64 bf16 + pad)
#define W_RS 272              // bytes per k-row (128 bf16 + pad)
#define AH_OFF 0
#define AL_OFF (AH_OFF + 128*A_RS)       // 18432
#define WH_OFF (AL_OFF + 128*A_RS)       // 36864
#define WL_OFF (WH_OFF + 64*W_RS)        // 54272
#define TCG_SMEM (WL_OFF + 64*W_RS)      // 71680 bytes

template<int MODE>
__global__ __launch_bounds__(256) void mma_gemm(const float* __restrict__ Ain,
                                                const float* __restrict__ W,
                                                const float* __restrict__ bias,
                                                float* __restrict__ C, int N) {
    extern __shared__ char sm[];
    // CRITICAL: __device__ symbols must be bound in device code, never host.
    const float* A = (MODE == 1) ? (const float*)g_attn : Ain;

    const int tid = threadIdx.x;
    const int warp = tid >> 5, lane = tid & 31;
    const int wm = (warp >> 1) * 32;     // warp m-offset in CTA tile
    const int wn = (warp & 1) * 64;      // warp n-offset
    const int n0 = blockIdx.x * 128;
    const int m0 = blockIdx.y * 128;

    const int sel = lane >> 3, rr = lane & 7;
    const uint32_t smAH = smem_u32(sm + AH_OFF);
    const uint32_t smAL = smem_u32(sm + AL_OFF);
    const uint32_t smWH = smem_u32(sm + WH_OFF);
    const uint32_t smWL = smem_u32(sm + WL_OFF);
    // ldmatrix per-lane address components
    const uint32_t aOff = (uint32_t)(((sel & 1) * 8 + rr) * A_RS + (sel >> 1) * 16);
    const uint32_t bOff = (uint32_t)(((sel & 1) * 8 + rr) * W_RS + (sel >> 1) * 16);

    float acc[2][8][4];
#pragma unroll
    for (int mi = 0; mi < 2; mi++)
#pragma unroll
        for (int ni = 0; ni < 8; ni++)
#pragma unroll
            for (int j = 0; j < 4; j++) acc[mi][ni][j] = 0.f;

    for (int c = 0; c < 16; c++) {
        const int k0 = c * 64;
        if (c) __syncthreads();          // prev chunk's ldmatrix reads done

        // ---- A chunk: 128 m x 64 k fp32 -> Ah/Al bf16 [m][k]
#pragma unroll
        for (int i = 0; i < 8; i++) {
            int t = tid + i * 256;       // 0..2047
            int m = t >> 4, kq = t & 15;
            float4 v = *(const float4*)(A + (size_t)(m0 + m) * DD + k0 + kq * 4);
            uint32_t h0, l0, h1, l1;
            split2(v.x, v.y, h0, l0);
            split2(v.z, v.w, h1, l1);
            *(uint2*)(sm + AH_OFF + m * A_RS + kq * 8) = make_uint2(h0, h1);
            *(uint2*)(sm + AL_OFF + m * A_RS + kq * 8) = make_uint2(l0, l1);
        }

        // ---- W chunk: 64 k x 128 n fp32 -> Wh/Wl bf16 [k][n]
#pragma unroll
        for (int i = 0; i < 8; i++) {
            int t = tid + i * 256;       // 0..2047
            int k = t >> 5, n4 = t & 31;
            float4 v = *(const float4*)(W + (size_t)(k0 + k) * N + n0 + n4 * 4);
            uint32_t h0, l0, h1, l1;
            split2(v.x, v.y, h0, l0);
            split2(v.z, v.w, h1, l1);
            *(uint2*)(sm + WH_OFF + k * W_RS + n4 * 8) = make_uint2(h0, h1);
            *(uint2*)(sm + WL_OFF + k * W_RS + n4 * 8) = make_uint2(l0, l1);
        }
        __syncthreads();

        // ---- MMA phase: 4 k-steps of 16 bf16
#pragma unroll
        for (int ks = 0; ks < 4; ks++) {
            uint32_t ah[2][4], al[2][4], bh[4][4], bl[4][4];
#pragma unroll
            for (int mi = 0; mi < 2; mi++) {
                uint32_t ad = aOff + (uint32_t)((wm + mi * 16) * A_RS + ks * 32);
                ldsm4(smAH + ad, ah[mi]);
                ldsm4(smAL + ad, al[mi]);
            }
#pragma unroll
            for (int ng = 0; ng < 4; ng++) {
                uint32_t bd = bOff + (uint32_t)(ks * 16 * W_RS + (wn + ng * 16) * 2);
                ldsm4t(smWH + bd, bh[ng]);
                ldsm4t(smWL + bd, bl[ng]);
            }
#pragma unroll
            for (int mi = 0; mi < 2; mi++)
#pragma unroll
                for (int ng = 0; ng < 4; ng++) {
                    mma16816(acc[mi][2*ng],   ah[mi], bh[ng][0], bh[ng][1]);
                    mma16816(acc[mi][2*ng],   ah[mi], bl[ng][0], bl[ng][1]);
                    mma16816(acc[mi][2*ng],   al[mi], bh[ng][0], bh[ng][1]);
                    mma16816(acc[mi][2*ng+1], ah[mi], bh[ng][2], bh[ng][3]);
                    mma16816(acc[mi][2*ng+1], ah[mi], bl[ng][2], bl[ng][3]);
                    mma16816(acc[mi][2*ng+1], al[mi], bh[ng][2], bh[ng][3]);
                }
        }
    }

    // ---- Epilogue: C fragments -> gmem
    const int gid = lane >> 2, tig = lane & 3;
#pragma unroll
    for (int mi = 0; mi < 2; mi++) {
        int r0 = m0 + wm + mi * 16 + gid;     // rows r0 and r0+8
#pragma unroll
        for (int ni = 0; ni < 8; ni++) {
            int col = n0 + wn + ni * 8 + tig * 2;
            float bv0 = bias[col], bv1 = bias[col + 1];
            float v00 = acc[mi][ni][0] + bv0, v01 = acc[mi][ni][1] + bv1;
            float v10 = acc[mi][ni][2] + bv0, v11 = acc[mi][ni][3] + bv1;
            if (MODE == 0) {
                const int part = n0 >> 10;
                const int dcol = col & 1023;
                const int h = dcol >> 6, hd = dcol & 63;
                float* base = (part == 0) ? g_q : (part == 1) ? g_k : g_v;
                if (part == 0) { v00 *= 0.125f; v01 *= 0.125f; v10 *= 0.125f; v11 *= 0.125f; }
                int b0_ = r0 >> 11, s0_ = r0 & 2047;
                int r1 = r0 + 8;
                int b1_ = r1 >> 11, s1_ = r1 & 2047;
                *(float2*)(base + ((size_t)(b0_ * HH + h) * SS + s0_) * HDIM + hd) =
                    make_float2(v00, v01);
                *(float2*)(base + ((size_t)(b1_ * HH + h) * SS + s1_) * HDIM + hd) =
                    make_float2(v10, v11);
            } else {
                *(float2*)(C + (size_t)r0 * DD + col)       = make_float2(v00, v01);
                *(float2*)(C + (size_t)(r0 + 8) * DD + col) = make_float2(v10, v11);
            }
        }
    }
}

// ---------------------------------------------------------------------------
// Flash attention, fp32, causal. 64x64 tiles. 256 threads. (unchanged, passing)
// ---------------------------------------------------------------------------
#define QS_STRIDE 65
#define KT_STRIDE 68
#define PS_STRIDE 65
#define SMEM_FLOATS (64*QS_STRIDE + 64*KT_STRIDE + 64*64 + 64*PS_STRIDE)

__global__ __launch_bounds__(256, 2) void attn_kernel() {
    extern __shared__ float smf[];
    float* Qs = smf;
    float* Kt = Qs + 64 * QS_STRIDE;
    float* Vs = Kt + 64 * KT_STRIDE;
    float* Ps = Vs + 64 * 64;

    const int qt = blockIdx.x;
    const int bh = blockIdx.y;
    const int tid = threadIdx.x;
    const int r = tid >> 2;
    const int c0 = (tid & 3) * 16;

    const float* Qg = g_q + (size_t)bh * SS * HDIM;
    const float* Kg = g_k + (size_t)bh * SS * HDIM;
    const float* Vg = g_v + (size_t)bh * SS * HDIM;

    for (int t = tid; t < 64 * 16; t += 256) {
        int rr = t >> 4, cc = (t & 15) * 4;
        float4 v = *(const float4*)(Qg + ((size_t)(qt * 64 + rr)) * HDIM + cc);
        Qs[rr * QS_STRIDE + cc + 0] = v.x;
        Qs[rr * QS_STRIDE + cc + 1] = v.y;
        Qs[rr * QS_STRIDE + cc + 2] = v.z;
        Qs[rr * QS_STRIDE + cc + 3] = v.w;
    }
    __syncthreads();

    float m = -INFINITY, l = 0.f;
    float o[16];
#pragma unroll
    for (int i = 0; i < 16; i++) o[i] = 0.f;

    for (int j = 0; j <= qt; j++) {
        for (int t = tid; t < 64 * 16; t += 256) {
            int rr = t >> 4, cc = (t & 15) * 4;
            size_t gofs = ((size_t)(j * 64 + rr)) * HDIM + cc;
            float4 kv = *(const float4*)(Kg + gofs);
            Kt[(cc + 0) * KT_STRIDE + rr] = kv.x;
            Kt[(cc + 1) * KT_STRIDE + rr] = kv.y;
            Kt[(cc + 2) * KT_STRIDE + rr] = kv.z;
            Kt[(cc + 3) * KT_STRIDE + rr] = kv.w;
            float4 vv = *(const float4*)(Vg + gofs);
            *(float4*)&Vs[rr * 64 + cc] = vv;
        }
        __syncthreads();

        float s[16];
#pragma unroll
        for (int i = 0; i < 16; i++) s[i] = 0.f;
#pragma unroll 8
        for (int k = 0; k < 64; k++) {
            float qv = Qs[r * QS_STRIDE + k];
            float4 k0 = *(float4*)&Kt[k * KT_STRIDE + c0];
            float4 k1 = *(float4*)&Kt[k * KT_STRIDE + c0 + 4];
            float4 k2 = *(float4*)&Kt[k * KT_STRIDE + c0 + 8];
            float4 k3 = *(float4*)&Kt[k * KT_STRIDE + c0 + 12];
            s[0]  = fmaf(qv, k0.x, s[0]);  s[1]  = fmaf(qv, k0.y, s[1]);
            s[2]  = fmaf(qv, k0.z, s[2]);  s[3]  = fmaf(qv, k0.w, s[3]);
            s[4]  = fmaf(qv, k1.x, s[4]);  s[5]  = fmaf(qv, k1.y, s[5]);
            s[6]  = fmaf(qv, k1.z, s[6]);  s[7]  = fmaf(qv, k1.w, s[7]);
            s[8]  = fmaf(qv, k2.x, s[8]);  s[9]  = fmaf(qv, k2.y, s[9]);
            s[10] = fmaf(qv, k2.z, s[10]); s[11] = fmaf(qv, k2.w, s[11]);
            s[12] = fmaf(qv, k3.x, s[12]); s[13] = fmaf(qv, k3.y, s[13]);
            s[14] = fmaf(qv, k3.z, s[14]); s[15] = fmaf(qv, k3.w, s[15]);
        }

        if (j == qt) {
#pragma unroll
            for (int i = 0; i < 16; i++)
                if (c0 + i > r) s[i] = -INFINITY;
        }

        float mt = s[0];
#pragma unroll
        for (int i = 1; i < 16; i++) mt = fmaxf(mt, s[i]);
        mt = fmaxf(mt, __shfl_xor_sync(0xffffffffu, mt, 1));
        mt = fmaxf(mt, __shfl_xor_sync(0xffffffffu, mt, 2));
        float mnew = fmaxf(m, mt);
        float alpha = __expf(m - mnew);
        float rs = 0.f;
#pragma unroll
        for (int i = 0; i < 16; i++) {
            float p = __expf(s[i] - mnew);
            rs += p;
            Ps[r * PS_STRIDE + c0 + i] = p;
        }
        rs += __shfl_xor_sync(0xffffffffu, rs, 1);
        rs += __shfl_xor_sync(0xffffffffu, rs, 2);
        l = l * alpha + rs;
        m = mnew;
#pragma unroll
        for (int i = 0; i < 16; i++) o[i] *= alpha;
        __syncthreads();

#pragma unroll 8
        for (int k = 0; k < 64; k++) {
            float p = Ps[r * PS_STRIDE + k];
            float4 v0 = *(float4*)&Vs[k * 64 + c0];
            float4 v1 = *(float4*)&Vs[k * 64 + c0 + 4];
            float4 v2 = *(float4*)&Vs[k * 64 + c0 + 8];
            float4 v3 = *(float4*)&Vs[k * 64 + c0 + 12];
            o[0]  = fmaf(p, v0.x, o[0]);  o[1]  = fmaf(p, v0.y, o[1]);
            o[2]  = fmaf(p, v0.z, o[2]);  o[3]  = fmaf(p, v0.w, o[3]);
            o[4]  = fmaf(p, v1.x, o[4]);  o[5]  = fmaf(p, v1.y, o[5]);
            o[6]  = fmaf(p, v1.z, o[6]);  o[7]  = fmaf(p, v1.w, o[7]);
            o[8]  = fmaf(p, v2.x, o[8]);  o[9]  = fmaf(p, v2.y, o[9]);
            o[10] = fmaf(p, v2.z, o[10]); o[11] = fmaf(p, v2.w, o[11]);
            o[12] = fmaf(p, v3.x, o[12]); o[13] = fmaf(p, v3.y, o[13]);
            o[14] = fmaf(p, v3.z, o[14]); o[15] = fmaf(p, v3.w, o[15]);
        }
        __syncthreads();
    }

    float inv = 1.f / l;
#pragma unroll
    for (int i = 0; i < 16; i++) o[i] *= inv;

    int b_ = bh >> 4, h = bh & 15;
    float* op = g_attn + ((size_t)(b_ * SS + qt * 64 + r)) * DD + h * 64 + c0;
    *(float4*)(op)      = make_float4(o[0],  o[1],  o[2],  o[3]);
    *(float4*)(op + 4)  = make_float4(o[4],  o[5],  o[6],  o[7]);
    *(float4*)(op + 8)  = make_float4(o[8],  o[9],  o[10], o[11]);
    *(float4*)(op + 12) = make_float4(o[12], o[13], o[14], o[15]);
}

// ---------------------------------------------------------------------------
extern "C" void kernel_launch(void* const* d_in, const int* in_sizes, int n_in,
                              void* d_out, int out_size) {
    const float* x     = (const float*)d_in[0];
    const float* W_qkv = (const float*)d_in[1];
    const float* b_qkv = (const float*)d_in[2];
    const float* W_out = (const float*)d_in[3];
    const float* b_out = (const float*)d_in[4];
    float* out = (float*)d_out;

    cudaFuncSetAttribute(mma_gemm<0>, cudaFuncAttributeMaxDynamicSharedMemorySize, TCG_SMEM);
    cudaFuncSetAttribute(mma_gemm<1>, cudaFuncAttributeMaxDynamicSharedMemorySize, TCG_SMEM);

    mma_gemm<0><<<dim3(3 * DD / 128, MR / 128), 256, TCG_SMEM>>>(x, W_qkv, b_qkv, nullptr, 3 * DD);

    size_t smem = (size_t)SMEM_FLOATS * sizeof(float);
    cudaFuncSetAttribute(attn_kernel, cudaFuncAttributeMaxDynamicSharedMemorySize, (int)smem);
    attn_kernel<<<dim3(SS / 64, BB * HH), 256, smem>>>();

    mma_gemm<1><<<dim3(DD / 128, MR / 128), 256, TCG_SMEM>>>(nullptr, W_out, b_out, out, DD);
}

// round 7
// speedup vs baseline: 4.7532x; 3.9307x over previous
#include <cuda_runtime.h>
#include <cuda_bf16.h>
#include <math.h>
#include <stdint.h>

#define BB 4
#define SS 2048
#define DD 1024
#define HH 16
#define HDIM 64
#define MR (BB*SS)          // 8192 rows

// Scratch (allocation-free: device globals)
__device__ float g_q[(size_t)BB*HH*SS*HDIM];   // head-major, pre-scaled by 0.125
__device__ float g_k[(size_t)BB*HH*SS*HDIM];
__device__ float g_v[(size_t)BB*HH*SS*HDIM];
__device__ float g_attn[(size_t)MR*DD];        // [B*S, D] for out-proj

// ---------------------------------------------------------------------------
// Warp-MMA helpers (baseline PTX ISA only: works on plain sm_103 target)
// ---------------------------------------------------------------------------
__device__ __forceinline__ uint32_t smem_u32(const void* p) {
    uint32_t a;
    asm("{ .reg .u64 t; cvta.to.shared.u64 t, %1; cvt.u32.u64 %0, t; }"
        : "=r"(a) : "l"(p));
    return a;
}

__device__ __forceinline__ void ldsm4(uint32_t addr, uint32_t r[4]) {
    asm volatile("ldmatrix.sync.aligned.m8n8.x4.shared.b16 {%0,%1,%2,%3}, [%4];"
                 : "=r"(r[0]), "=r"(r[1]), "=r"(r[2]), "=r"(r[3]) : "r"(addr) : "memory");
}
__device__ __forceinline__ void ldsm4t(uint32_t addr, uint32_t r[4]) {
    asm volatile("ldmatrix.sync.aligned.m8n8.x4.trans.shared.b16 {%0,%1,%2,%3}, [%4];"
                 : "=r"(r[0]), "=r"(r[1]), "=r"(r[2]), "=r"(r[3]) : "r"(addr) : "memory");
}
__device__ __forceinline__ void mma16816(float d[4], const uint32_t a[4],
                                         uint32_t b0, uint32_t b1) {
    asm volatile(
        "mma.sync.aligned.m16n8k16.row.col.f32.bf16.bf16.f32 "
        "{%0,%1,%2,%3}, {%4,%5,%6,%7}, {%8,%9}, {%0,%1,%2,%3};"
        : "+f"(d[0]), "+f"(d[1]), "+f"(d[2]), "+f"(d[3])
        : "r"(a[0]), "r"(a[1]), "r"(a[2]), "r"(a[3]), "r"(b0), "r"(b1));
}

// split two fp32 into packed bf16 hi pair + lo (residual) pair
__device__ __forceinline__ void split2(float x, float y, uint32_t& h, uint32_t& l) {
    __nv_bfloat16 hx = __float2bfloat16(x), hy = __float2bfloat16(y);
    float rx = x - __bfloat162float(hx);
    float ry = y - __bfloat162float(hy);
    __nv_bfloat16 lx = __float2bfloat16(rx), ly = __float2bfloat16(ry);
    h = (uint32_t)__bfloat16_as_ushort(hx) | ((uint32_t)__bfloat16_as_ushort(hy) << 16);
    l = (uint32_t)__bfloat16_as_ushort(lx) | ((uint32_t)__bfloat16_as_ushort(ly) << 16);
}

// ---------------------------------------------------------------------------
// HMMA GEMM (unchanged from round 6, passing): C = A @ W + bias, bf16x3.
// ---------------------------------------------------------------------------
#define A_RS 144
#define W_RS 272
#define AH_OFF 0
#define AL_OFF (AH_OFF + 128*A_RS)
#define WH_OFF (AL_OFF + 128*A_RS)
#define WL_OFF (WH_OFF + 64*W_RS)
#define TCG_SMEM (WL_OFF + 64*W_RS)

template<int MODE>
__global__ __launch_bounds__(256) void mma_gemm(const float* __restrict__ Ain,
                                                const float* __restrict__ W,
                                                const float* __restrict__ bias,
                                                float* __restrict__ C, int N) {
    extern __shared__ char sm[];
    const float* A = (MODE == 1) ? (const float*)g_attn : Ain;

    const int tid = threadIdx.x;
    const int warp = tid >> 5, lane = tid & 31;
    const int wm = (warp >> 1) * 32;
    const int wn = (warp & 1) * 64;
    const int n0 = blockIdx.x * 128;
    const int m0 = blockIdx.y * 128;

    const int sel = lane >> 3, rr = lane & 7;
    const uint32_t smAH = smem_u32(sm + AH_OFF);
    const uint32_t smAL = smem_u32(sm + AL_OFF);
    const uint32_t smWH = smem_u32(sm + WH_OFF);
    const uint32_t smWL = smem_u32(sm + WL_OFF);
    const uint32_t aOff = (uint32_t)(((sel & 1) * 8 + rr) * A_RS + (sel >> 1) * 16);
    const uint32_t bOff = (uint32_t)(((sel & 1) * 8 + rr) * W_RS + (sel >> 1) * 16);

    float acc[2][8][4];
#pragma unroll
    for (int mi = 0; mi < 2; mi++)
#pragma unroll
        for (int ni = 0; ni < 8; ni++)
#pragma unroll
            for (int j = 0; j < 4; j++) acc[mi][ni][j] = 0.f;

    for (int c = 0; c < 16; c++) {
        const int k0 = c * 64;
        if (c) __syncthreads();

#pragma unroll
        for (int i = 0; i < 8; i++) {
            int t = tid + i * 256;
            int m = t >> 4, kq = t & 15;
            float4 v = *(const float4*)(A + (size_t)(m0 + m) * DD + k0 + kq * 4);
            uint32_t h0, l0, h1, l1;
            split2(v.x, v.y, h0, l0);
            split2(v.z, v.w, h1, l1);
            *(uint2*)(sm + AH_OFF + m * A_RS + kq * 8) = make_uint2(h0, h1);
            *(uint2*)(sm + AL_OFF + m * A_RS + kq * 8) = make_uint2(l0, l1);
        }
#pragma unroll
        for (int i = 0; i < 8; i++) {
            int t = tid + i * 256;
            int k = t >> 5, n4 = t & 31;
            float4 v = *(const float4*)(W + (size_t)(k0 + k) * N + n0 + n4 * 4);
            uint32_t h0, l0, h1, l1;
            split2(v.x, v.y, h0, l0);
            split2(v.z, v.w, h1, l1);
            *(uint2*)(sm + WH_OFF + k * W_RS + n4 * 8) = make_uint2(h0, h1);
            *(uint2*)(sm + WL_OFF + k * W_RS + n4 * 8) = make_uint2(l0, l1);
        }
        __syncthreads();

#pragma unroll
        for (int ks = 0; ks < 4; ks++) {
            uint32_t ah[2][4], al[2][4], bh[4][4], bl[4][4];
#pragma unroll
            for (int mi = 0; mi < 2; mi++) {
                uint32_t ad = aOff + (uint32_t)((wm + mi * 16) * A_RS + ks * 32);
                ldsm4(smAH + ad, ah[mi]);
                ldsm4(smAL + ad, al[mi]);
            }
#pragma unroll
            for (int ng = 0; ng < 4; ng++) {
                uint32_t bd = bOff + (uint32_t)(ks * 16 * W_RS + (wn + ng * 16) * 2);
                ldsm4t(smWH + bd, bh[ng]);
                ldsm4t(smWL + bd, bl[ng]);
            }
#pragma unroll
            for (int mi = 0; mi < 2; mi++)
#pragma unroll
                for (int ng = 0; ng < 4; ng++) {
                    mma16816(acc[mi][2*ng],   ah[mi], bh[ng][0], bh[ng][1]);
                    mma16816(acc[mi][2*ng],   ah[mi], bl[ng][0], bl[ng][1]);
                    mma16816(acc[mi][2*ng],   al[mi], bh[ng][0], bh[ng][1]);
                    mma16816(acc[mi][2*ng+1], ah[mi], bh[ng][2], bh[ng][3]);
                    mma16816(acc[mi][2*ng+1], ah[mi], bl[ng][2], bl[ng][3]);
                    mma16816(acc[mi][2*ng+1], al[mi], bh[ng][2], bh[ng][3]);
                }
        }
    }

    const int gid = lane >> 2, tig = lane & 3;
#pragma unroll
    for (int mi = 0; mi < 2; mi++) {
        int r0 = m0 + wm + mi * 16 + gid;
#pragma unroll
        for (int ni = 0; ni < 8; ni++) {
            int col = n0 + wn + ni * 8 + tig * 2;
            float bv0 = bias[col], bv1 = bias[col + 1];
            float v00 = acc[mi][ni][0] + bv0, v01 = acc[mi][ni][1] + bv1;
            float v10 = acc[mi][ni][2] + bv0, v11 = acc[mi][ni][3] + bv1;
            if (MODE == 0) {
                const int part = n0 >> 10;
                const int dcol = col & 1023;
                const int h = dcol >> 6, hd = dcol & 63;
                float* base = (part == 0) ? g_q : (part == 1) ? g_k : g_v;
                if (part == 0) { v00 *= 0.125f; v01 *= 0.125f; v10 *= 0.125f; v11 *= 0.125f; }
                int b0_ = r0 >> 11, s0_ = r0 & 2047;
                int r1 = r0 + 8;
                int b1_ = r1 >> 11, s1_ = r1 & 2047;
                *(float2*)(base + ((size_t)(b0_ * HH + h) * SS + s0_) * HDIM + hd) =
                    make_float2(v00, v01);
                *(float2*)(base + ((size_t)(b1_ * HH + h) * SS + s1_) * HDIM + hd) =
                    make_float2(v10, v11);
            } else {
                *(float2*)(C + (size_t)r0 * DD + col)       = make_float2(v00, v01);
                *(float2*)(C + (size_t)(r0 + 8) * DD + col) = make_float2(v10, v11);
            }
        }
    }
}

// ---------------------------------------------------------------------------
// HMMA flash attention, causal, bf16x3 splits for QK^T and PV.
// CTA: 128 queries (8 warps x 16 rows), kv tiles of 64 keys.
// K smem [key][hd] -> non-trans ldmatrix B-frags (pairs r0/r2, r1/r3).
// V smem [key][hd] = [k][n] -> trans ldmatrix (GEMM-verified pattern).
// P stays register-resident via the C-frag -> A-frag identity.
// ---------------------------------------------------------------------------
#define K_RS 144
// smem regions (bytes): Q phase: Qh 0..18432, Ql 18432..36864
// KV phase: Kh 0, Kl 9216, Vh 18432, Vl 27648
__global__ __launch_bounds__(256) void attn_mma() {
    __shared__ char sm[36864];
    const int tid = threadIdx.x;
    const int warp = tid >> 5, lane = tid & 31;
    const int qt = blockIdx.x, bh = blockIdx.y;
    const int m0 = qt * 128;
    const int gid = lane >> 2, tig = lane & 3;
    const int sel = lane >> 3, rr = lane & 7;
    const uint32_t frOff = (uint32_t)(((sel & 1) * 8 + rr) * K_RS + (sel >> 1) * 16);
    const uint32_t smb = smem_u32(sm);

    const float* Qg = g_q + (size_t)bh * SS * HDIM;
    const float* Kg = g_k + (size_t)bh * SS * HDIM;
    const float* Vg = g_v + (size_t)bh * SS * HDIM;

    // ---- stage Q (128x64 fp32 -> bf16 hi/lo), extract A-frags per warp
#pragma unroll
    for (int i = 0; i < 8; i++) {
        int t = tid + i * 256;
        int row = t >> 4, q4 = t & 15;
        float4 v = *(const float4*)(Qg + (size_t)(m0 + row) * HDIM + q4 * 4);
        uint32_t h0, l0, h1, l1;
        split2(v.x, v.y, h0, l0);
        split2(v.z, v.w, h1, l1);
        *(uint2*)(sm + row * K_RS + q4 * 8)         = make_uint2(h0, h1);
        *(uint2*)(sm + 18432 + row * K_RS + q4 * 8) = make_uint2(l0, l1);
    }
    __syncthreads();
    uint32_t qh[4][4], ql[4][4];
#pragma unroll
    for (int ks = 0; ks < 4; ks++) {
        uint32_t ad = frOff + (uint32_t)(warp * 16 * K_RS + ks * 32);
        ldsm4(smb + ad, qh[ks]);
        ldsm4(smb + 18432 + ad, ql[ks]);
    }

    float mrow[2] = {-INFINITY, -INFINITY};
    float lrow[2] = {0.f, 0.f};
    float o[8][4];
#pragma unroll
    for (int ng = 0; ng < 8; ng++)
#pragma unroll
        for (int e = 0; e < 4; e++) o[ng][e] = 0.f;

    const int r_lo = m0 + warp * 16 + gid;
    const int r_hi = r_lo + 8;
    const int jmax = 2 * qt + 1;

    for (int j = 0; j <= jmax; j++) {
        __syncthreads();    // prior ldsm reads (Q frags / prev KV) complete
        // ---- load K,V tiles 64x64 fp32 -> bf16 hi/lo smem
#pragma unroll
        for (int i = 0; i < 4; i++) {
            int t = tid + i * 256;
            int row = t >> 4, q4 = t & 15;
            size_t go = (size_t)(j * 64 + row) * HDIM + q4 * 4;
            float4 kv = *(const float4*)(Kg + go);
            uint32_t h0, l0, h1, l1;
            split2(kv.x, kv.y, h0, l0);
            split2(kv.z, kv.w, h1, l1);
            *(uint2*)(sm + row * K_RS + q4 * 8)        = make_uint2(h0, h1);
            *(uint2*)(sm + 9216 + row * K_RS + q4 * 8) = make_uint2(l0, l1);
            float4 vv = *(const float4*)(Vg + go);
            split2(vv.x, vv.y, h0, l0);
            split2(vv.z, vv.w, h1, l1);
            *(uint2*)(sm + 18432 + row * K_RS + q4 * 8) = make_uint2(h0, h1);
            *(uint2*)(sm + 27648 + row * K_RS + q4 * 8) = make_uint2(l0, l1);
        }
        __syncthreads();

        // ---- S = Q @ K^T (warp: 16 q x 64 k)
        float s[8][4];
#pragma unroll
        for (int ng = 0; ng < 8; ng++)
#pragma unroll
            for (int e = 0; e < 4; e++) s[ng][e] = 0.f;
#pragma unroll
        for (int ks = 0; ks < 4; ks++) {
#pragma unroll
            for (int kg = 0; kg < 4; kg++) {
                uint32_t kd = frOff + (uint32_t)(kg * 16 * K_RS + ks * 32);
                uint32_t kh4[4], kl4[4];
                ldsm4(smb + kd, kh4);
                ldsm4(smb + 9216 + kd, kl4);
                mma16816(s[2*kg],   qh[ks], kh4[0], kh4[2]);
                mma16816(s[2*kg],   qh[ks], kl4[0], kl4[2]);
                mma16816(s[2*kg],   ql[ks], kh4[0], kh4[2]);
                mma16816(s[2*kg+1], qh[ks], kh4[1], kh4[3]);
                mma16816(s[2*kg+1], qh[ks], kl4[1], kl4[3]);
                mma16816(s[2*kg+1], ql[ks], kh4[1], kh4[3]);
            }
        }

        // ---- causal mask (only diagonal-region tiles)
        if (j >= 2 * qt) {
#pragma unroll
            for (int ng = 0; ng < 8; ng++) {
                int cg = j * 64 + ng * 8 + tig * 2;
                if (cg     > r_lo) s[ng][0] = -INFINITY;
                if (cg + 1 > r_lo) s[ng][1] = -INFINITY;
                if (cg     > r_hi) s[ng][2] = -INFINITY;
                if (cg + 1 > r_hi) s[ng][3] = -INFINITY;
            }
        }

        // ---- online softmax (2 rows/thread; row spread over lane quad)
        float mt0 = -INFINITY, mt1 = -INFINITY;
#pragma unroll
        for (int ng = 0; ng < 8; ng++) {
            mt0 = fmaxf(mt0, fmaxf(s[ng][0], s[ng][1]));
            mt1 = fmaxf(mt1, fmaxf(s[ng][2], s[ng][3]));
        }
        mt0 = fmaxf(mt0, __shfl_xor_sync(0xffffffffu, mt0, 1));
        mt0 = fmaxf(mt0, __shfl_xor_sync(0xffffffffu, mt0, 2));
        mt1 = fmaxf(mt1, __shfl_xor_sync(0xffffffffu, mt1, 1));
        mt1 = fmaxf(mt1, __shfl_xor_sync(0xffffffffu, mt1, 2));
        float mn0 = fmaxf(mrow[0], mt0), mn1 = fmaxf(mrow[1], mt1);
        float a0 = __expf(mrow[0] - mn0), a1 = __expf(mrow[1] - mn1);
        float rs0 = 0.f, rs1 = 0.f;
#pragma unroll
        for (int ng = 0; ng < 8; ng++) {
            s[ng][0] = __expf(s[ng][0] - mn0);
            s[ng][1] = __expf(s[ng][1] - mn0);
            s[ng][2] = __expf(s[ng][2] - mn1);
            s[ng][3] = __expf(s[ng][3] - mn1);
            rs0 += s[ng][0] + s[ng][1];
            rs1 += s[ng][2] + s[ng][3];
        }
        rs0 += __shfl_xor_sync(0xffffffffu, rs0, 1);
        rs0 += __shfl_xor_sync(0xffffffffu, rs0, 2);
        rs1 += __shfl_xor_sync(0xffffffffu, rs1, 1);
        rs1 += __shfl_xor_sync(0xffffffffu, rs1, 2);
        lrow[0] = lrow[0] * a0 + rs0;
        lrow[1] = lrow[1] * a1 + rs1;
        mrow[0] = mn0; mrow[1] = mn1;
#pragma unroll
        for (int ng = 0; ng < 8; ng++) {
            o[ng][0] *= a0; o[ng][1] *= a0;
            o[ng][2] *= a1; o[ng][3] *= a1;
        }

        // ---- O += P @ V  (P from C->A frag identity, bf16 hi/lo split)
#pragma unroll
        for (int kc = 0; kc < 4; kc++) {
            uint32_t pha[4], pla[4];
            split2(s[2*kc][0],   s[2*kc][1],   pha[0], pla[0]);
            split2(s[2*kc][2],   s[2*kc][3],   pha[1], pla[1]);
            split2(s[2*kc+1][0], s[2*kc+1][1], pha[2], pla[2]);
            split2(s[2*kc+1][2], s[2*kc+1][3], pha[3], pla[3]);
#pragma unroll
            for (int hg = 0; hg < 4; hg++) {
                uint32_t vd = frOff + (uint32_t)(kc * 16 * K_RS + hg * 32);
                uint32_t vh4[4], vl4[4];
                ldsm4t(smb + 18432 + vd, vh4);
                ldsm4t(smb + 27648 + vd, vl4);
                mma16816(o[2*hg],   pha, vh4[0], vh4[1]);
                mma16816(o[2*hg],   pha, vl4[0], vl4[1]);
                mma16816(o[2*hg],   pla, vh4[0], vh4[1]);
                mma16816(o[2*hg+1], pha, vh4[2], vh4[3]);
                mma16816(o[2*hg+1], pha, vl4[2], vl4[3]);
                mma16816(o[2*hg+1], pla, vh4[2], vh4[3]);
            }
        }
    }

    // ---- write O / l  -> g_attn [B*S, D]
    const float inv0 = 1.f / lrow[0], inv1 = 1.f / lrow[1];
    const int b_ = bh >> 4, h = bh & 15;
#pragma unroll
    for (int ng = 0; ng < 8; ng++) {
        int col = h * 64 + ng * 8 + tig * 2;
        *(float2*)(g_attn + ((size_t)(b_ * SS + r_lo)) * DD + col) =
            make_float2(o[ng][0] * inv0, o[ng][1] * inv0);
        *(float2*)(g_attn + ((size_t)(b_ * SS + r_hi)) * DD + col) =
            make_float2(o[ng][2] * inv1, o[ng][3] * inv1);
    }
}

// ---------------------------------------------------------------------------
extern "C" void kernel_launch(void* const* d_in, const int* in_sizes, int n_in,
                              void* d_out, int out_size) {
    const float* x     = (const float*)d_in[0];
    const float* W_qkv = (const float*)d_in[1];
    const float* b_qkv = (const float*)d_in[2];
    const float* W_out = (const float*)d_in[3];
    const float* b_out = (const float*)d_in[4];
    float* out = (float*)d_out;

    cudaFuncSetAttribute(mma_gemm<0>, cudaFuncAttributeMaxDynamicSharedMemorySize, TCG_SMEM);
    cudaFuncSetAttribute(mma_gemm<1>, cudaFuncAttributeMaxDynamicSharedMemorySize, TCG_SMEM);

    mma_gemm<0><<<dim3(3 * DD / 128, MR / 128), 256, TCG_SMEM>>>(x, W_qkv, b_qkv, nullptr, 3 * DD);

    attn_mma<<<dim3(SS / 128, BB * HH), 256>>>();

    mma_gemm<1><<<dim3(DD / 128, MR / 128), 256, TCG_SMEM>>>(nullptr, W_out, b_out, out, DD);
}

// round 8
// speedup vs baseline: 5.9190x; 1.2453x over previous
#include <cuda_runtime.h>
#include <cuda_bf16.h>
#include <math.h>
#include <stdint.h>

#define BB 4
#define SS 2048
#define DD 1024
#define HH 16
#define HDIM 64
#define MR (BB*SS)          // 8192 rows

typedef unsigned short ushortt;

// Scratch (allocation-free: device globals). All bf16 hi/lo split pairs.
__device__ ushortt g_xh[(size_t)MR*DD],  g_xl[(size_t)MR*DD];          // x
__device__ ushortt g_wqh[(size_t)DD*3*DD], g_wql[(size_t)DD*3*DD];     // W_qkv
__device__ ushortt g_woh[(size_t)DD*DD], g_wol[(size_t)DD*DD];         // W_out
__device__ ushortt g_qh[(size_t)BB*HH*SS*HDIM], g_ql[(size_t)BB*HH*SS*HDIM];
__device__ ushortt g_kh[(size_t)BB*HH*SS*HDIM], g_kl[(size_t)BB*HH*SS*HDIM];
__device__ ushortt g_vh[(size_t)BB*HH*SS*HDIM], g_vl[(size_t)BB*HH*SS*HDIM];
__device__ ushortt g_attnh[(size_t)MR*DD], g_attnl[(size_t)MR*DD];

// ---------------------------------------------------------------------------
// helpers (baseline PTX ISA only: plain sm_103 target)
// ---------------------------------------------------------------------------
__device__ __forceinline__ uint32_t smem_u32(const void* p) {
    uint32_t a;
    asm("{ .reg .u64 t; cvta.to.shared.u64 t, %1; cvt.u32.u64 %0, t; }"
        : "=r"(a) : "l"(p));
    return a;
}
__device__ __forceinline__ void ldsm4(uint32_t addr, uint32_t r[4]) {
    asm volatile("ldmatrix.sync.aligned.m8n8.x4.shared.b16 {%0,%1,%2,%3}, [%4];"
                 : "=r"(r[0]), "=r"(r[1]), "=r"(r[2]), "=r"(r[3]) : "r"(addr) : "memory");
}
__device__ __forceinline__ void ldsm4t(uint32_t addr, uint32_t r[4]) {
    asm volatile("ldmatrix.sync.aligned.m8n8.x4.trans.shared.b16 {%0,%1,%2,%3}, [%4];"
                 : "=r"(r[0]), "=r"(r[1]), "=r"(r[2]), "=r"(r[3]) : "r"(addr) : "memory");
}
__device__ __forceinline__ void mma16816(float d[4], const uint32_t a[4],
                                         uint32_t b0, uint32_t b1) {
    asm volatile(
        "mma.sync.aligned.m16n8k16.row.col.f32.bf16.bf16.f32 "
        "{%0,%1,%2,%3}, {%4,%5,%6,%7}, {%8,%9}, {%0,%1,%2,%3};"
        : "+f"(d[0]), "+f"(d[1]), "+f"(d[2]), "+f"(d[3])
        : "r"(a[0]), "r"(a[1]), "r"(a[2]), "r"(a[3]), "r"(b0), "r"(b1));
}
__device__ __forceinline__ void split2(float x, float y, uint32_t& h, uint32_t& l) {
    __nv_bfloat16 hx = __float2bfloat16(x), hy = __float2bfloat16(y);
    float rx = x - __bfloat162float(hx);
    float ry = y - __bfloat162float(hy);
    __nv_bfloat16 lx = __float2bfloat16(rx), ly = __float2bfloat16(ry);
    h = (uint32_t)__bfloat16_as_ushort(hx) | ((uint32_t)__bfloat16_as_ushort(hy) << 16);
    l = (uint32_t)__bfloat16_as_ushort(lx) | ((uint32_t)__bfloat16_as_ushort(ly) << 16);
}
__device__ __forceinline__ void cp_async16(uint32_t dst, const void* src) {
    asm volatile("cp.async.cg.shared.global [%0], [%1], 16;" :: "r"(dst), "l"(src));
}
__device__ __forceinline__ void cp_commit() {
    asm volatile("cp.async.commit_group;" ::: "memory");
}
__device__ __forceinline__ void cp_wait0() {
    asm volatile("cp.async.wait_group 0;" ::: "memory");
}

// ---------------------------------------------------------------------------
// Pre-convert: fp32 -> bf16 hi/lo pair (vectorized, memory-bound)
// ---------------------------------------------------------------------------
__global__ void cvt_kernel(const float* __restrict__ src, ushortt* __restrict__ h,
                           ushortt* __restrict__ l, int n4) {
    int i = blockIdx.x * blockDim.x + threadIdx.x;
    if (i < n4) {
        float4 v = ((const float4*)src)[i];
        uint32_t h0, l0, h1, l1;
        split2(v.x, v.y, h0, l0);
        split2(v.z, v.w, h1, l1);
        ((uint2*)h)[i] = make_uint2(h0, h1);
        ((uint2*)l)[i] = make_uint2(l0, l1);
    }
}

// ---------------------------------------------------------------------------
// HMMA GEMM, bf16 inputs, cp.async 2-stage pipeline.
// CTA 128x128, BK=64 (16 chunks). 8 warps, warp tile 32x64.
// MODE 0: A=g_xh/l, W=g_wqh/l (N=3072), scatter bf16 q/k/v (q *0.125).
// MODE 1: A=g_attnh/l, W=g_woh/l (N=1024), fp32 out + bias.
// ---------------------------------------------------------------------------
#define A_RS 144              // 64 bf16 = 128B + 16 pad
#define W_RS 272              // 128 bf16 = 256B + 16 pad
#define GA_H 0
#define GA_L 18432
#define GW_H 36864
#define GW_L 54272
#define STAGE_SZ 71680
#define GEMM_SMEM (2*STAGE_SZ)   // 143360

template<int MODE>
__global__ __launch_bounds__(256) void mma_gemm(const float* __restrict__ bias,
                                                float* __restrict__ C, int N) {
    extern __shared__ char sm[];
    const ushortt* Ah = (MODE == 0) ? g_xh : g_attnh;
    const ushortt* Al = (MODE == 0) ? g_xl : g_attnl;
    const ushortt* Wh = (MODE == 0) ? g_wqh : g_woh;
    const ushortt* Wl = (MODE == 0) ? g_wql : g_wol;

    const int tid = threadIdx.x;
    const int warp = tid >> 5, lane = tid & 31;
    const int wm = (warp >> 1) * 32;
    const int wn = (warp & 1) * 64;
    const int n0 = blockIdx.x * 128;
    const int m0 = blockIdx.y * 128;
    const uint32_t smb = smem_u32(sm);

    const int sel = lane >> 3, rr = lane & 7;
    const uint32_t aOff = (uint32_t)(((sel & 1) * 8 + rr) * A_RS + (sel >> 1) * 16);
    const uint32_t bOff = (uint32_t)(((sel & 1) * 8 + rr) * W_RS + (sel >> 1) * 16);

    // prefetch one chunk into stage st
#define GEMM_PREFETCH(st, c) do {                                          \
        uint32_t base_ = smb + (st) * STAGE_SZ;                            \
        int k0_ = (c) * 64;                                                \
        _Pragma("unroll")                                                  \
        for (int i_ = 0; i_ < 4; i_++) {                                   \
            int t_ = tid + i_ * 256;                                       \
            int row_ = t_ >> 3, cg_ = t_ & 7;                              \
            size_t g_ = (size_t)(m0 + row_) * DD + k0_ + cg_ * 8;          \
            uint32_t d_ = base_ + row_ * A_RS + cg_ * 16;                  \
            cp_async16(d_ + GA_H, Ah + g_);                                \
            cp_async16(d_ + GA_L, Al + g_);                                \
        }                                                                  \
        _Pragma("unroll")                                                  \
        for (int i_ = 0; i_ < 4; i_++) {                                   \
            int t_ = tid + i_ * 256;                                       \
            int row_ = t_ >> 4, cg_ = t_ & 15;                             \
            size_t g_ = (size_t)(k0_ + row_) * N + n0 + cg_ * 8;           \
            uint32_t d_ = base_ + row_ * W_RS + cg_ * 16;                  \
            cp_async16(d_ + GW_H, Wh + g_);                                \
            cp_async16(d_ + GW_L, Wl + g_);                                \
        }                                                                  \
    } while (0)

    float acc[2][8][4];
#pragma unroll
    for (int mi = 0; mi < 2; mi++)
#pragma unroll
        for (int ni = 0; ni < 8; ni++)
#pragma unroll
            for (int j = 0; j < 4; j++) acc[mi][ni][j] = 0.f;

    GEMM_PREFETCH(0, 0);
    cp_commit();

    for (int c = 0; c < 16; c++) {
        cp_wait0();
        __syncthreads();
        if (c + 1 < 16) {
            GEMM_PREFETCH((c + 1) & 1, c + 1);
            cp_commit();
        }
        const uint32_t sb = smb + (c & 1) * STAGE_SZ;

#pragma unroll
        for (int ks = 0; ks < 4; ks++) {
            uint32_t ah[2][4], al[2][4], bh[4][4], bl[4][4];
#pragma unroll
            for (int mi = 0; mi < 2; mi++) {
                uint32_t ad = aOff + (uint32_t)((wm + mi * 16) * A_RS + ks * 32);
                ldsm4(sb + GA_H + ad, ah[mi]);
                ldsm4(sb + GA_L + ad, al[mi]);
            }
#pragma unroll
            for (int ng = 0; ng < 4; ng++) {
                uint32_t bd = bOff + (uint32_t)(ks * 16 * W_RS + (wn + ng * 16) * 2);
                ldsm4t(sb + GW_H + bd, bh[ng]);
                ldsm4t(sb + GW_L + bd, bl[ng]);
            }
#pragma unroll
            for (int mi = 0; mi < 2; mi++)
#pragma unroll
                for (int ng = 0; ng < 4; ng++) {
                    mma16816(acc[mi][2*ng],   ah[mi], bh[ng][0], bh[ng][1]);
                    mma16816(acc[mi][2*ng],   ah[mi], bl[ng][0], bl[ng][1]);
                    mma16816(acc[mi][2*ng],   al[mi], bh[ng][0], bh[ng][1]);
                    mma16816(acc[mi][2*ng+1], ah[mi], bh[ng][2], bh[ng][3]);
                    mma16816(acc[mi][2*ng+1], ah[mi], bl[ng][2], bl[ng][3]);
                    mma16816(acc[mi][2*ng+1], al[mi], bh[ng][2], bh[ng][3]);
                }
        }
        __syncthreads();   // all warps done reading this stage before c+2 overwrites
    }

    // ---- Epilogue
    const int gid = lane >> 2, tig = lane & 3;
#pragma unroll
    for (int mi = 0; mi < 2; mi++) {
        int r0 = m0 + wm + mi * 16 + gid;
#pragma unroll
        for (int ni = 0; ni < 8; ni++) {
            int col = n0 + wn + ni * 8 + tig * 2;
            float bv0 = bias[col], bv1 = bias[col + 1];
            float v00 = acc[mi][ni][0] + bv0, v01 = acc[mi][ni][1] + bv1;
            float v10 = acc[mi][ni][2] + bv0, v11 = acc[mi][ni][3] + bv1;
            if (MODE == 0) {
                const int part = n0 >> 10;
                const int dcol = col & 1023;
                const int h = dcol >> 6, hd = dcol & 63;
                ushortt* bh_ = (part == 0) ? g_qh : (part == 1) ? g_kh : g_vh;
                ushortt* bl_ = (part == 0) ? g_ql : (part == 1) ? g_kl : g_vl;
                if (part == 0) { v00 *= 0.125f; v01 *= 0.125f; v10 *= 0.125f; v11 *= 0.125f; }
                int b0_ = r0 >> 11, s0_ = r0 & 2047;
                int r1 = r0 + 8;
                int b1_ = r1 >> 11, s1_ = r1 & 2047;
                size_t o0 = ((size_t)(b0_ * HH + h) * SS + s0_) * HDIM + hd;
                size_t o1 = ((size_t)(b1_ * HH + h) * SS + s1_) * HDIM + hd;
                uint32_t ph, pl;
                split2(v00, v01, ph, pl);
                *(uint32_t*)(bh_ + o0) = ph;  *(uint32_t*)(bl_ + o0) = pl;
                split2(v10, v11, ph, pl);
                *(uint32_t*)(bh_ + o1) = ph;  *(uint32_t*)(bl_ + o1) = pl;
            } else {
                *(float2*)(C + (size_t)r0 * DD + col)       = make_float2(v00, v01);
                *(float2*)(C + (size_t)(r0 + 8) * DD + col) = make_float2(v10, v11);
            }
        }
    }
}

// ---------------------------------------------------------------------------
// HMMA flash attention, bf16 pre-split inputs, cp.async KV double buffer.
// CTA: 128 queries (8 warps x 16), kv tiles of 64.
// stage s (s*36864): KH 0, KL 9216, VH 18432, VL 27648 (each 64 x 144B).
// Q staged once in stage-1 region, frags kept in registers.
// Output: g_attnh/g_attnl (bf16 split) for the out-proj GEMM.
// ---------------------------------------------------------------------------
#define K_RS 144
#define ATT_STAGE 36864
#define ATT_SMEM (2*ATT_STAGE)    // 73728

__global__ __launch_bounds__(256) void attn_mma() {
    extern __shared__ char sm[];
    const int tid = threadIdx.x;
    const int warp = tid >> 5, lane = tid & 31;
    const int qt = blockIdx.x, bh = blockIdx.y;
    const int m0 = qt * 128;
    const int gid = lane >> 2, tig = lane & 3;
    const int sel = lane >> 3, rr = lane & 7;
    const uint32_t frOff = (uint32_t)(((sel & 1) * 8 + rr) * K_RS + (sel >> 1) * 16);
    const uint32_t smb = smem_u32(sm);

    const size_t hb = (size_t)bh * SS * HDIM;
    const ushortt* Qh = g_qh + hb;  const ushortt* Ql = g_ql + hb;
    const ushortt* Kh = g_kh + hb;  const ushortt* Kl = g_kl + hb;
    const ushortt* Vh = g_vh + hb;  const ushortt* Vl = g_vl + hb;

#define ATT_PREFETCH(st, j) do {                                            \
        uint32_t base_ = smb + (st) * ATT_STAGE;                            \
        _Pragma("unroll")                                                   \
        for (int i_ = 0; i_ < 2; i_++) {                                    \
            int t_ = tid + i_ * 256;                                        \
            int row_ = t_ >> 3, cg_ = t_ & 7;                               \
            size_t g_ = (size_t)((j) * 64 + row_) * HDIM + cg_ * 8;         \
            uint32_t d_ = base_ + row_ * K_RS + cg_ * 16;                   \
            cp_async16(d_,         Kh + g_);                                \
            cp_async16(d_ + 9216,  Kl + g_);                                \
            cp_async16(d_ + 18432, Vh + g_);                                \
            cp_async16(d_ + 27648, Vl + g_);                                \
        }                                                                   \
    } while (0)

    // prefetch KV tile 0 into stage 0 immediately
    ATT_PREFETCH(0, 0);
    cp_commit();

    // ---- stage Q (bf16) into stage-1 region, extract A-frags
#pragma unroll
    for (int i = 0; i < 4; i++) {
        int t = tid + i * 256;           // 0..1023
        int row = t >> 3, cg = t & 7;
        size_t g = (size_t)(m0 + row) * HDIM + cg * 8;
        uint32_t d = smb + ATT_STAGE + row * K_RS + cg * 16;
        *(uint4*)(sm + (d - smb))         = *(const uint4*)(Qh + g);
        *(uint4*)(sm + (d - smb) + 18432) = *(const uint4*)(Ql + g);
    }
    __syncthreads();
    uint32_t qh[4][4], ql[4][4];
#pragma unroll
    for (int ks = 0; ks < 4; ks++) {
        uint32_t ad = smb + ATT_STAGE + frOff + (uint32_t)(warp * 16 * K_RS + ks * 32);
        ldsm4(ad, qh[ks]);
        ldsm4(ad + 18432, ql[ks]);
    }
    __syncthreads();   // Q region free for j=1 prefetch

    float mrow[2] = {-INFINITY, -INFINITY};
    float lrow[2] = {0.f, 0.f};
    float o[8][4];
#pragma unroll
    for (int ng = 0; ng < 8; ng++)
#pragma unroll
        for (int e = 0; e < 4; e++) o[ng][e] = 0.f;

    const int r_lo = m0 + warp * 16 + gid;
    const int r_hi = r_lo + 8;
    const int jmax = 2 * qt + 1;

    for (int j = 0; j <= jmax; j++) {
        cp_wait0();
        __syncthreads();
        if (j < jmax) {
            ATT_PREFETCH((j + 1) & 1, j + 1);
            cp_commit();
        }
        const uint32_t sb = smb + (j & 1) * ATT_STAGE;

        // ---- S = Q @ K^T
        float s[8][4];
#pragma unroll
        for (int ng = 0; ng < 8; ng++)
#pragma unroll
            for (int e = 0; e < 4; e++) s[ng][e] = 0.f;
#pragma unroll
        for (int ks = 0; ks < 4; ks++) {
#pragma unroll
            for (int kg = 0; kg < 4; kg++) {
                uint32_t kd = sb + frOff + (uint32_t)(kg * 16 * K_RS + ks * 32);
                uint32_t kh4[4], kl4[4];
                ldsm4(kd, kh4);
                ldsm4(kd + 9216, kl4);
                mma16816(s[2*kg],   qh[ks], kh4[0], kh4[2]);
                mma16816(s[2*kg],   qh[ks], kl4[0], kl4[2]);
                mma16816(s[2*kg],   ql[ks], kh4[0], kh4[2]);
                mma16816(s[2*kg+1], qh[ks], kh4[1], kh4[3]);
                mma16816(s[2*kg+1], qh[ks], kl4[1], kl4[3]);
                mma16816(s[2*kg+1], ql[ks], kh4[1], kh4[3]);
            }
        }

        // ---- causal mask
        if (j >= 2 * qt) {
#pragma unroll
            for (int ng = 0; ng < 8; ng++) {
                int cg = j * 64 + ng * 8 + tig * 2;
                if (cg     > r_lo) s[ng][0] = -INFINITY;
                if (cg + 1 > r_lo) s[ng][1] = -INFINITY;
                if (cg     > r_hi) s[ng][2] = -INFINITY;
                if (cg + 1 > r_hi) s[ng][3] = -INFINITY;
            }
        }

        // ---- online softmax
        float mt0 = -INFINITY, mt1 = -INFINITY;
#pragma unroll
        for (int ng = 0; ng < 8; ng++) {
            mt0 = fmaxf(mt0, fmaxf(s[ng][0], s[ng][1]));
            mt1 = fmaxf(mt1, fmaxf(s[ng][2], s[ng][3]));
        }
        mt0 = fmaxf(mt0, __shfl_xor_sync(0xffffffffu, mt0, 1));
        mt0 = fmaxf(mt0, __shfl_xor_sync(0xffffffffu, mt0, 2));
        mt1 = fmaxf(mt1, __shfl_xor_sync(0xffffffffu, mt1, 1));
        mt1 = fmaxf(mt1, __shfl_xor_sync(0xffffffffu, mt1, 2));
        float mn0 = fmaxf(mrow[0], mt0), mn1 = fmaxf(mrow[1], mt1);
        float a0 = __expf(mrow[0] - mn0), a1 = __expf(mrow[1] - mn1);
        float rs0 = 0.f, rs1 = 0.f;
#pragma unroll
        for (int ng = 0; ng < 8; ng++) {
            s[ng][0] = __expf(s[ng][0] - mn0);
            s[ng][1] = __expf(s[ng][1] - mn0);
            s[ng][2] = __expf(s[ng][2] - mn1);
            s[ng][3] = __expf(s[ng][3] - mn1);
            rs0 += s[ng][0] + s[ng][1];
            rs1 += s[ng][2] + s[ng][3];
        }
        rs0 += __shfl_xor_sync(0xffffffffu, rs0, 1);
        rs0 += __shfl_xor_sync(0xffffffffu, rs0, 2);
        rs1 += __shfl_xor_sync(0xffffffffu, rs1, 1);
        rs1 += __shfl_xor_sync(0xffffffffu, rs1, 2);
        lrow[0] = lrow[0] * a0 + rs0;
        lrow[1] = lrow[1] * a1 + rs1;
        mrow[0] = mn0; mrow[1] = mn1;
#pragma unroll
        for (int ng = 0; ng < 8; ng++) {
            o[ng][0] *= a0; o[ng][1] *= a0;
            o[ng][2] *= a1; o[ng][3] *= a1;
        }

        // ---- O += P @ V  (P: C-frag -> A-frag identity, bf16x3)
#pragma unroll
        for (int kc = 0; kc < 4; kc++) {
            uint32_t pha[4], pla[4];
            split2(s[2*kc][0],   s[2*kc][1],   pha[0], pla[0]);
            split2(s[2*kc][2],   s[2*kc][3],   pha[1], pla[1]);
            split2(s[2*kc+1][0], s[2*kc+1][1], pha[2], pla[2]);
            split2(s[2*kc+1][2], s[2*kc+1][3], pha[3], pla[3]);
#pragma unroll
            for (int hg = 0; hg < 4; hg++) {
                uint32_t vd = sb + frOff + (uint32_t)(kc * 16 * K_RS + hg * 32);
                uint32_t vh4[4], vl4[4];
                ldsm4t(vd + 18432, vh4);
                ldsm4t(vd + 27648, vl4);
                mma16816(o[2*hg],   pha, vh4[0], vh4[1]);
                mma16816(o[2*hg],   pha, vl4[0], vl4[1]);
                mma16816(o[2*hg],   pla, vh4[0], vh4[1]);
                mma16816(o[2*hg+1], pha, vh4[2], vh4[3]);
                mma16816(o[2*hg+1], pha, vl4[2], vl4[3]);
                mma16816(o[2*hg+1], pla, vh4[2], vh4[3]);
            }
        }
        __syncthreads();   // stage reads done before j+2 prefetch overwrites
    }

    // ---- write O (bf16 split) -> g_attnh/g_attnl [B*S, D]
    const float inv0 = 1.f / lrow[0], inv1 = 1.f / lrow[1];
    const int b_ = bh >> 4, h = bh & 15;
#pragma unroll
    for (int ng = 0; ng < 8; ng++) {
        int col = h * 64 + ng * 8 + tig * 2;
        size_t o0 = ((size_t)(b_ * SS + r_lo)) * DD + col;
        size_t o1 = ((size_t)(b_ * SS + r_hi)) * DD + col;
        uint32_t ph, pl;
        split2(o[ng][0] * inv0, o[ng][1] * inv0, ph, pl);
        *(uint32_t*)(g_attnh + o0) = ph;  *(uint32_t*)(g_attnl + o0) = pl;
        split2(o[ng][2] * inv1, o[ng][3] * inv1, ph, pl);
        *(uint32_t*)(g_attnh + o1) = ph;  *(uint32_t*)(g_attnl + o1) = pl;
    }
}

// ---------------------------------------------------------------------------
// cvt launcher shims (bind __device__ symbols in device code)
// ---------------------------------------------------------------------------
__global__ void cvt_x_kernel(const float* __restrict__ src, int n4) {
    int i = blockIdx.x * blockDim.x + threadIdx.x;
    if (i < n4) {
        float4 v = ((const float4*)src)[i];
        uint32_t h0, l0, h1, l1;
        split2(v.x, v.y, h0, l0); split2(v.z, v.w, h1, l1);
        ((uint2*)g_xh)[i] = make_uint2(h0, h1);
        ((uint2*)g_xl)[i] = make_uint2(l0, l1);
    }
}
__global__ void cvt_wq_kernel(const float* __restrict__ src, int n4) {
    int i = blockIdx.x * blockDim.x + threadIdx.x;
    if (i < n4) {
        float4 v = ((const float4*)src)[i];
        uint32_t h0, l0, h1, l1;
        split2(v.x, v.y, h0, l0); split2(v.z, v.w, h1, l1);
        ((uint2*)g_wqh)[i] = make_uint2(h0, h1);
        ((uint2*)g_wql)[i] = make_uint2(l0, l1);
    }
}
__global__ void cvt_wo_kernel(const float* __restrict__ src, int n4) {
    int i = blockIdx.x * blockDim.x + threadIdx.x;
    if (i < n4) {
        float4 v = ((const float4*)src)[i];
        uint32_t h0, l0, h1, l1;
        split2(v.x, v.y, h0, l0); split2(v.z, v.w, h1, l1);
        ((uint2*)g_woh)[i] = make_uint2(h0, h1);
        ((uint2*)g_wol)[i] = make_uint2(l0, l1);
    }
}

// ---------------------------------------------------------------------------
extern "C" void kernel_launch(void* const* d_in, const int* in_sizes, int n_in,
                              void* d_out, int out_size) {
    const float* x     = (const float*)d_in[0];
    const float* W_qkv = (const float*)d_in[1];
    const float* b_qkv = (const float*)d_in[2];
    const float* W_out = (const float*)d_in[3];
    const float* b_out = (const float*)d_in[4];
    float* out = (float*)d_out;

    cudaFuncSetAttribute(mma_gemm<0>, cudaFuncAttributeMaxDynamicSharedMemorySize, GEMM_SMEM);
    cudaFuncSetAttribute(mma_gemm<1>, cudaFuncAttributeMaxDynamicSharedMemorySize, GEMM_SMEM);
    cudaFuncSetAttribute(attn_mma,    cudaFuncAttributeMaxDynamicSharedMemorySize, ATT_SMEM);

    {
        int n4 = MR * DD / 4;
        cvt_x_kernel<<<(n4 + 255) / 256, 256>>>(x, n4);
    }
    {
        int n4 = DD * 3 * DD / 4;
        cvt_wq_kernel<<<(n4 + 255) / 256, 256>>>(W_qkv, n4);
    }
    {
        int n4 = DD * DD / 4;
        cvt_wo_kernel<<<(n4 + 255) / 256, 256>>>(W_out, n4);
    }

    mma_gemm<0><<<dim3(3 * DD / 128, MR / 128), 256, GEMM_SMEM>>>(b_qkv, nullptr, 3 * DD);

    attn_mma<<<dim3(SS / 128, BB * HH), 256, ATT_SMEM>>>();

    mma_gemm<1><<<dim3(DD / 128, MR / 128), 256, GEMM_SMEM>>>(b_out, out, DD);
}